// round 13
// baseline (speedup 1.0000x reference)
#include <cuda_runtime.h>
#include <cuda_bf16.h>
#include <math.h>
#include <stdint.h>

#define NN 10000
#define NE 160000
#define CC 128
#define DD 64
#define HID 256
#define TPWN 512
#define MROW 1024          // m0 (256) + m1 (256*3)
#define SC_OFF (NN * 512)  // message is N*128*4 = N*512 floats, sc follows

#define KP1 448            // layer-1 virtual K': [hi 136+8p | lo 136+8p | hi 136+8p | 16p]
#define KPH 768            // hidden virtual K': [hi 256 | lo 256 | hi 256]
#define KACT 512           // stored activation cols: [hi 256 | lo 256]

// -------- device scratch (allocation-free rule: static __device__ globals) ----
// Only referenced from device code (host-side use binds the host shadow; round-5 bug).
__device__ float g_u0[NN * CC];
__device__ float g_u1[NN * CC * 3];
__device__ float g_down[NN * DD];
__device__ float g_m[NN * MROW];

__device__ __align__(16) __nv_bfloat16 g_act0[(size_t)NE * KACT];  // ping [hi|lo]
__device__ __align__(16) __nv_bfloat16 g_act1[(size_t)NE * KACT];  // pong
__device__ __align__(16) __nv_bfloat16 g_w1T[HID * KP1];           // W1^T split [256][448]
__device__ __align__(16) __nv_bfloat16 g_w2T[HID * KPH];           // [256][768] [hi|hi|lo]
__device__ __align__(16) __nv_bfloat16 g_w3T[HID * KPH];
__device__ __align__(16) __nv_bfloat16 g_w4T[TPWN * KPH];          // [512][768]

// ======================= warp-MMA helpers (sm_80+ ISA only) =================
__device__ __forceinline__ uint32_t smem_u32(const void* p) {
    uint32_t a;
    asm("{ .reg .u64 t; cvta.to.shared.u64 t, %1; cvt.u32.u64 %0, t; }" : "=r"(a) : "l"(p));
    return a;
}
#define SW128(off) ((off) ^ (((off) >> 3) & 0x70))

__device__ __forceinline__ void ldm_x4(uint32_t* r, uint32_t addr) {
    asm volatile("ldmatrix.sync.aligned.m8n8.x4.shared.b16 {%0,%1,%2,%3}, [%4];"
                 : "=r"(r[0]), "=r"(r[1]), "=r"(r[2]), "=r"(r[3]) : "r"(addr));
}
__device__ __forceinline__ void mma16816(float* c, const uint32_t* a, const uint32_t* b) {
    asm volatile(
        "mma.sync.aligned.m16n8k16.row.col.f32.bf16.bf16.f32 "
        "{%0,%1,%2,%3}, {%4,%5,%6,%7}, {%8,%9}, {%0,%1,%2,%3};"
        : "+f"(c[0]), "+f"(c[1]), "+f"(c[2]), "+f"(c[3])
        : "r"(a[0]), "r"(a[1]), "r"(a[2]), "r"(a[3]), "r"(b[0]), "r"(b[1]));
}
__device__ __forceinline__ void cp16(uint32_t dst, const void* src) {
    asm volatile("cp.async.cg.shared.global [%0], [%1], 16;" :: "r"(dst), "l"(src));
}
#define CP_COMMIT() asm volatile("cp.async.commit_group;" ::: "memory")
#define CP_WAIT1()  asm volatile("cp.async.wait_group 1;" ::: "memory")
#define CP_WAIT0()  asm volatile("cp.async.wait_group 0;" ::: "memory")

// ---------------------------------------------------------------------------
// zero the segment-sum accumulator (must run every launch: deterministic)
// ---------------------------------------------------------------------------
__global__ void zero_m_kernel() {
    int idx = blockIdx.x * blockDim.x + threadIdx.x;
    int stride = gridDim.x * blockDim.x;
    float4 z = make_float4(0.f, 0.f, 0.f, 0.f);
    float4* p = (float4*)g_m;
    for (int i = idx; i < NN * MROW / 4; i += stride) p[i] = z;
}

// ---------------------------------------------------------------------------
// Node transforms: u0, u1, down (to scratch) + sc (directly to output)
// ---------------------------------------------------------------------------
__global__ void node_kernel(const float* __restrict__ nf,
                            const float* __restrict__ Wu0,
                            const float* __restrict__ Wu1,
                            const float* __restrict__ Wd,
                            const float* __restrict__ Ws0,
                            const float* __restrict__ Ws1,
                            float* __restrict__ out) {
    const int NB = 8;
    __shared__ float sx0[NB][CC];
    __shared__ float sx1[NB][CC * 3];
    int n0 = blockIdx.x * NB;
    int v = threadIdx.x;  // 0..127

    for (int j = v; j < NB * 512; j += 128) {
        int nb = j >> 9;
        int k = j & 511;
        float val = nf[(size_t)(n0 + nb) * 512 + k];
        if (k < 128) sx0[nb][k] = val;
        else sx1[nb][k - 128] = val;
    }
    __syncthreads();

    const float inv_c = 0.08838834764831845f;  // 1/sqrt(128)

    float au0[NB], as0[NB], ad[NB];
#pragma unroll
    for (int nb = 0; nb < NB; nb++) { au0[nb] = 0.f; as0[nb] = 0.f; ad[nb] = 0.f; }
    for (int u = 0; u < CC; u++) {
        float w0 = Wu0[u * CC + v];
        float ws = Ws0[u * CC + v];
        float wd = (v < DD) ? Wd[u * DD + v] : 0.f;
#pragma unroll
        for (int nb = 0; nb < NB; nb++) {
            float x = sx0[nb][u];
            au0[nb] += x * w0;
            as0[nb] += x * ws;
            ad[nb] += x * wd;
        }
    }
#pragma unroll
    for (int nb = 0; nb < NB; nb++) {
        int n = n0 + nb;
        g_u0[n * CC + v] = au0[nb] * inv_c;
        out[SC_OFF + (size_t)n * 512 + v] = as0[nb] * inv_c;
        if (v < DD) g_down[n * DD + v] = ad[nb] * inv_c;
    }

    float au1[NB][3], as1[NB][3];
#pragma unroll
    for (int nb = 0; nb < NB; nb++)
#pragma unroll
        for (int i = 0; i < 3; i++) { au1[nb][i] = 0.f; as1[nb][i] = 0.f; }
    for (int u = 0; u < CC; u++) {
        float wu = Wu1[u * CC + v];
        float ws = Ws1[u * CC + v];
#pragma unroll
        for (int nb = 0; nb < NB; nb++) {
#pragma unroll
            for (int i = 0; i < 3; i++) {
                float x = sx1[nb][u * 3 + i];
                au1[nb][i] += x * wu;
                as1[nb][i] += x * ws;
            }
        }
    }
#pragma unroll
    for (int nb = 0; nb < NB; nb++) {
        int n = n0 + nb;
#pragma unroll
        for (int i = 0; i < 3; i++) {
            g_u1[n * (CC * 3) + v * 3 + i] = au1[nb][i] * inv_c;
            out[SC_OFF + (size_t)n * 512 + 128 + v * 3 + i] = as1[nb][i] * inv_c;
        }
    }
}

// ---------------------------------------------------------------------------
// Weight prep: transpose to [N][K'] K-major bf16 with split segments.
// ---------------------------------------------------------------------------
__global__ void prep_w1(const float* __restrict__ w) {  // [136][256] -> g_w1T [256][448]
    int i = blockIdx.x * blockDim.x + threadIdx.x;
    if (i >= HID * KP1) return;
    int n = i / KP1, k = i % KP1;
    __nv_bfloat16 o = __float2bfloat16(0.f);
    if (k < 432) {
        int seg = k / 144, rem = k % 144;
        if (rem < 136) {
            float v = w[rem * HID + n];
            __nv_bfloat16 h = __float2bfloat16(v);
            o = (seg < 2) ? h : __float2bfloat16(v - __bfloat162float(h));
        }
    }
    g_w1T[n * KP1 + k] = o;
}

template <int WSEL>  // 2,3,4
__global__ void prep_w_hid(const float* __restrict__ w, int Nc) {
    int i = blockIdx.x * blockDim.x + threadIdx.x;
    if (i >= Nc * KPH) return;
    int n = i / KPH, k = i % KPH;
    int seg = k >> 8, rem = k & 255;
    float v = w[rem * Nc + n];
    __nv_bfloat16 h = __float2bfloat16(v);
    __nv_bfloat16 o = (seg < 2) ? h : __float2bfloat16(v - __bfloat162float(h));
    __nv_bfloat16* dst = (WSEL == 2) ? g_w2T : (WSEL == 3) ? g_w3T : g_w4T;
    dst[(size_t)n * KPH + k] = o;
}

// ---------------------------------------------------------------------------
// HMMA GEMM: C[128 x 128 tile] = A'[M,K'] @ W'[N,K']^T, fp32 accum.
// 8 warps: 4(M) x 2(N) -> warp tile 32x64. mma.m16n8k16 bf16, ldmatrix feeds.
// 3-stage cp.async ring, K staged 64 bf16 (128B SW128 rows).
// SRC 0: A gathered+split on the fly from fp32 (edge_feats | down[s] | down[r]).
// SRC 1/2: A = g_act0/g_act1 stored [hi|lo]; virtual col>=512 re-reads hi.
// DST 0/1 -> silu + bf16 hi/lo split into g_act0/g_act1.
// DST 3   -> FUSED tensor-product + scatter: blockIdx.x = TP weight quarter
//            (w0|w1|w2|w3); fragments feed atomicAdds into g_m directly.
// ---------------------------------------------------------------------------
template <int SRC, int WSEL, int DST, int KPRM, bool SILU>
__global__ void __launch_bounds__(256)
mma_gemm(float scale, const float* __restrict__ ef, const int* __restrict__ eidx,
         const float* __restrict__ ea) {
    const __nv_bfloat16* __restrict__ A =
        (SRC == 1) ? g_act0 : (SRC == 2) ? g_act1 : nullptr;
    const __nv_bfloat16* __restrict__ W =
        (WSEL == 1) ? g_w1T : (WSEL == 2) ? g_w2T : (WSEL == 3) ? g_w3T : g_w4T;
    const int WK = (WSEL == 1) ? KP1 : KPH;  // weight row stride

    extern __shared__ char smem[];
    const int BOFF = 49152;  // A: 3 x 16KB, B: 3 x 16KB
    uint32_t sb = smem_u32(smem);

    int tid = threadIdx.x;
    int lane = tid & 31, wid = tid >> 5;
    int wm = wid & 3;        // 0..3 -> M offset wm*32
    int wn = wid >> 2;       // 0..1 -> N offset wn*64
    int rowBase = blockIdx.y * 128;
    int colBase = blockIdx.x * 128;
    const int S = KPRM / 64;

    float acc[2][8][4];
#pragma unroll
    for (int i = 0; i < 2; i++)
#pragma unroll
        for (int j = 0; j < 8; j++)
#pragma unroll
            for (int q = 0; q < 4; q++) acc[i][j][q] = 0.f;

    // ---- stage loader: A tile 128x64 bf16 + B tile 128x64 bf16, SW128 ----
    auto load_stage = [&](int ks, int buf) {
        char* as = smem + buf * 16384;
        uint32_t bBase = sb + BOFF + buf * 16384;
        uint32_t aBase = sb + buf * 16384;
#pragma unroll
        for (int c = 0; c < 4; c++) {
            int idx = tid + c * 256;           // 0..1023
            int row = idx >> 3, cb = idx & 7;  // 128 rows x 8 chunks of 8 bf16
            int c0 = ks * 64 + cb * 8;
            uint32_t so = SW128((uint32_t)(row * 128 + cb * 16));
            // ---- A ----
            if (SRC == 0) {
                float v[8];
                bool zero = (c0 >= 432);
                int seg = 0;
                if (!zero) {
                    seg = c0 / 144;            // 0,1,2
                    int j = c0 - seg * 144;
                    const float* src = nullptr;
                    int e = rowBase + row;
                    if (j < 8) src = ef + (size_t)e * 8 + j;
                    else if (j < 72) src = g_down + (size_t)eidx[e] * DD + (j - 8);
                    else if (j < 136) src = g_down + (size_t)eidx[NE + e] * DD + (j - 72);
                    else zero = true;          // pad cols 136..143 within segment
                    if (!zero) {
                        float4 v0 = *(const float4*)src;
                        float4 v1 = *(const float4*)(src + 4);
                        v[0] = v0.x; v[1] = v0.y; v[2] = v0.z; v[3] = v0.w;
                        v[4] = v1.x; v[5] = v1.y; v[6] = v1.z; v[7] = v1.w;
                    }
                }
                uint4 wv;
                if (zero) {
                    wv = make_uint4(0u, 0u, 0u, 0u);
                } else {
                    uint32_t pk[4];
#pragma unroll
                    for (int t = 0; t < 4; t++) {
                        __nv_bfloat16 h0 = __float2bfloat16(v[2 * t]);
                        __nv_bfloat16 h1 = __float2bfloat16(v[2 * t + 1]);
                        __nv_bfloat162 p;
                        if (seg == 1) {
                            p.x = __float2bfloat16(v[2 * t] - __bfloat162float(h0));
                            p.y = __float2bfloat16(v[2 * t + 1] - __bfloat162float(h1));
                        } else {
                            p.x = h0; p.y = h1;
                        }
                        pk[t] = *(uint32_t*)&p;
                    }
                    wv = make_uint4(pk[0], pk[1], pk[2], pk[3]);
                }
                *(uint4*)(as + so) = wv;
            } else {
                int srccol = (c0 < KACT) ? c0 : c0 - KACT;  // hi copy re-read
                cp16(aBase + so, A + (size_t)(rowBase + row) * KACT + srccol);
            }
            // ---- B (always dense, cp.async) ----
            cp16(bBase + so, W + (size_t)(colBase + row) * WK + c0);
        }
        CP_COMMIT();
    };

    load_stage(0, 0);
    if (S > 1) load_stage(1, 1);

    for (int s = 0; s < S; s++) {
        if (s + 1 < S) { CP_WAIT1(); } else { CP_WAIT0(); }
        __syncthreads();

        int buf = s % 3;
        uint32_t aBase = sb + buf * 16384;
        uint32_t bBase = sb + BOFF + buf * 16384;
#pragma unroll
        for (int k16 = 0; k16 < 4; k16++) {
            uint32_t a[2][4];
#pragma unroll
            for (int mf = 0; mf < 2; mf++) {
                int r = wm * 32 + mf * 16 + (lane & 15);
                int kc = k16 * 16 + ((lane >> 4) << 3);
                ldm_x4(a[mf], aBase + SW128((uint32_t)(r * 128 + kc * 2)));
            }
            uint32_t b[8][2];
#pragma unroll
            for (int g = 0; g < 4; g++) {
                int nr = wn * 64 + g * 16 + (lane & 7) + ((lane >> 4) & 1) * 8;
                int kc = k16 * 16 + (((lane >> 3) & 1) << 3);
                uint32_t t4[4];
                ldm_x4(t4, bBase + SW128((uint32_t)(nr * 128 + kc * 2)));
                b[2 * g][0] = t4[0]; b[2 * g][1] = t4[1];
                b[2 * g + 1][0] = t4[2]; b[2 * g + 1][1] = t4[3];
            }
#pragma unroll
            for (int mf = 0; mf < 2; mf++)
#pragma unroll
                for (int nf = 0; nf < 8; nf++)
                    mma16816(acc[mf][nf], a[mf], b[nf]);
        }
        __syncthreads();  // all reads of buf done before refill

        if (s + 2 < S) load_stage(s + 2, (s + 2) % 3);
    }

    if (DST == 3) {
        // ---- fused tensor product + scatter (quarter q = blockIdx.x) ----
        const int q = blockIdx.x;
        const float rsqrt3 = 0.5773502691896258f;
#pragma unroll
        for (int mf = 0; mf < 2; mf++) {
#pragma unroll
            for (int rr = 0; rr < 2; rr++) {
                int e = rowBase + wm * 32 + mf * 16 + (lane >> 2) + rr * 8;
                int snd = eidx[e];
                int rcv = eidx[NE + e];
                float4 y = *(const float4*)(ea + (size_t)e * 4);
                float* mrow = g_m + (size_t)rcv * MROW;
                const float* u0row = g_u0 + (size_t)snd * CC;
                const float* u1row = g_u1 + (size_t)snd * (CC * 3);
#pragma unroll
                for (int nf = 0; nf < 8; nf++) {
#pragma unroll
                    for (int cc = 0; cc < 2; cc++) {
                        int c = wn * 64 + nf * 8 + (lane & 3) * 2 + cc;  // 0..127
                        float w = acc[mf][nf][rr * 2 + cc] * scale;
                        if (q == 0) {
                            atomicAdd(mrow + c, w * u0row[c] * y.x);
                        } else if (q == 1) {
                            float a = w * u0row[c];
                            atomicAdd(mrow + 256 + c * 3 + 0, a * y.y);
                            atomicAdd(mrow + 256 + c * 3 + 1, a * y.z);
                            atomicAdd(mrow + 256 + c * 3 + 2, a * y.w);
                        } else if (q == 2) {
                            float b = w * y.x;
                            atomicAdd(mrow + 256 + (128 + c) * 3 + 0, b * u1row[c * 3 + 0]);
                            atomicAdd(mrow + 256 + (128 + c) * 3 + 1, b * u1row[c * 3 + 1]);
                            atomicAdd(mrow + 256 + (128 + c) * 3 + 2, b * u1row[c * 3 + 2]);
                        } else {
                            float dot = u1row[c * 3 + 0] * y.y + u1row[c * 3 + 1] * y.z +
                                        u1row[c * 3 + 2] * y.w;
                            atomicAdd(mrow + 128 + c, w * dot * rsqrt3);
                        }
                    }
                }
            }
        }
        return;
    }

    // ---- epilogue (activation layers): frag (mf,nf): rows r0,r0+8; cols c0,c0+1 ----
#pragma unroll
    for (int mf = 0; mf < 2; mf++) {
#pragma unroll
        for (int nf = 0; nf < 8; nf++) {
            int r0 = rowBase + wm * 32 + mf * 16 + (lane >> 2);
            int c0 = colBase + wn * 64 + nf * 8 + (lane & 3) * 2;
            __nv_bfloat16* dst = (DST == 0) ? g_act0 : g_act1;
#pragma unroll
            for (int rr = 0; rr < 2; rr++) {
                float x0 = acc[mf][nf][rr * 2 + 0] * scale;
                float x1 = acc[mf][nf][rr * 2 + 1] * scale;
                if (SILU) {
                    x0 = x0 / (1.0f + expf(-x0));
                    x1 = x1 / (1.0f + expf(-x1));
                }
                __nv_bfloat16 h0 = __float2bfloat16(x0);
                __nv_bfloat16 h1 = __float2bfloat16(x1);
                __nv_bfloat162 hp; hp.x = h0; hp.y = h1;
                __nv_bfloat162 lp;
                lp.x = __float2bfloat16(x0 - __bfloat162float(h0));
                lp.y = __float2bfloat16(x1 - __bfloat162float(h1));
                __nv_bfloat16* p = dst + (size_t)(r0 + rr * 8) * KACT + c0;
                *(__nv_bfloat162*)(p) = hp;          // hi segment [0,256)
                *(__nv_bfloat162*)(p + 256) = lp;    // lo segment [256,512)
            }
        }
    }
}

// ---------------------------------------------------------------------------
// Final linear: message[n,v,0] = (m0 @ Wl0)/256 ; message[n,v,1..3] = (m1 @ Wl1)/256
// ---------------------------------------------------------------------------
__global__ void msg_kernel(const float* __restrict__ Wl0,
                           const float* __restrict__ Wl1,
                           float* __restrict__ out) {
    const int NB = 8;
    __shared__ float sm[NB][MROW];
    int n0 = blockIdx.x * NB;
    int v = threadIdx.x;

    for (int j = v; j < NB * MROW; j += 128) {
        sm[j >> 10][j & 1023] = g_m[(size_t)n0 * MROW + j];
    }
    __syncthreads();

    float m0acc[NB];
    float m1acc[NB][3];
#pragma unroll
    for (int nb = 0; nb < NB; nb++) {
        m0acc[nb] = 0.f;
#pragma unroll
        for (int i = 0; i < 3; i++) m1acc[nb][i] = 0.f;
    }

    for (int cc = 0; cc < 256; cc++) {
        float w0 = Wl0[cc * 128 + v];
        float w1 = Wl1[cc * 128 + v];
#pragma unroll
        for (int nb = 0; nb < NB; nb++) {
            m0acc[nb] += sm[nb][cc] * w0;
#pragma unroll
            for (int i = 0; i < 3; i++)
                m1acc[nb][i] += sm[nb][256 + cc * 3 + i] * w1;
        }
    }

    const float sc = 1.0f / 256.0f;  // (1/sqrt(256)) / AVG_NEIGH
#pragma unroll
    for (int nb = 0; nb < NB; nb++) {
        int n = n0 + nb;
        float4 v4;
        v4.x = m0acc[nb] * sc;
        v4.y = m1acc[nb][0] * sc;
        v4.z = m1acc[nb][1] * sc;
        v4.w = m1acc[nb][2] * sc;
        *(float4*)(out + (size_t)n * 512 + v * 4) = v4;
    }
}

// ---------------------------------------------------------------------------
extern "C" void kernel_launch(void* const* d_in, const int* in_sizes, int n_in,
                              void* d_out, int out_size) {
    const float* node_feats = (const float*)d_in[1];
    const float* edge_attrs = (const float*)d_in[2];
    const float* edge_feats = (const float*)d_in[3];
    const int*   edge_index = (const int*)d_in[4];
    const float* W_up0  = (const float*)d_in[5];
    const float* W_up1  = (const float*)d_in[6];
    const float* W_down = (const float*)d_in[7];
    const float* mlp_w1 = (const float*)d_in[8];
    const float* mlp_w2 = (const float*)d_in[9];
    const float* mlp_w3 = (const float*)d_in[10];
    const float* mlp_w4 = (const float*)d_in[11];
    const float* W_lin0 = (const float*)d_in[12];
    const float* W_lin1 = (const float*)d_in[13];
    const float* W_skip0 = (const float*)d_in[14];
    const float* W_skip1 = (const float*)d_in[15];
    float* out = (float*)d_out;

    const int MM_SMEM = 98304;  // 3x16KB A + 3x16KB B
    cudaFuncSetAttribute(mma_gemm<0, 1, 0, KP1, true>,
                         cudaFuncAttributeMaxDynamicSharedMemorySize, MM_SMEM);
    cudaFuncSetAttribute(mma_gemm<1, 2, 1, KPH, true>,
                         cudaFuncAttributeMaxDynamicSharedMemorySize, MM_SMEM);
    cudaFuncSetAttribute(mma_gemm<2, 3, 0, KPH, true>,
                         cudaFuncAttributeMaxDynamicSharedMemorySize, MM_SMEM);
    cudaFuncSetAttribute(mma_gemm<1, 4, 3, KPH, false>,
                         cudaFuncAttributeMaxDynamicSharedMemorySize, MM_SMEM);

    // 1) zero segment-sum accumulator (GEMM4 scatters into it)
    zero_m_kernel<<<1024, 256>>>();

    // 2) node transforms (+ sc output); produces g_down / g_u0 / g_u1
    node_kernel<<<NN / 8, 128>>>(node_feats, W_up0, W_up1, W_down, W_skip0, W_skip1, out);

    // 3) weight prep (transpose + bf16 hi/lo split)
    prep_w1<<<(HID * KP1 + 255) / 256, 256>>>(mlp_w1);
    prep_w_hid<2><<<(HID * KPH + 255) / 256, 256>>>(mlp_w2, HID);
    prep_w_hid<3><<<(HID * KPH + 255) / 256, 256>>>(mlp_w3, HID);
    prep_w_hid<4><<<(TPWN * KPH + 255) / 256, 256>>>(mlp_w4, TPWN);

    // 4) edge MLP on HMMA tensor cores; layer-1 gathers on the fly,
    //    layer-4 fuses the tensor product + scatter into its epilogue
    float scale1 = 1.0f / sqrtf(136.0f);
    float scale2 = 1.0f / 16.0f;
    {
        dim3 g(HID / 128, NE / 128);   // (2, 1250)
        mma_gemm<0, 1, 0, KP1, true><<<g, 256, MM_SMEM>>>(scale1, edge_feats, edge_index, nullptr);
        mma_gemm<1, 2, 1, KPH, true><<<g, 256, MM_SMEM>>>(scale2, nullptr, nullptr, nullptr);
        mma_gemm<2, 3, 0, KPH, true><<<g, 256, MM_SMEM>>>(scale2, nullptr, nullptr, nullptr);
    }
    {
        dim3 g(TPWN / 128, NE / 128);  // (4, 1250) — col quarter == TP weight group
        mma_gemm<1, 4, 3, KPH, false><<<g, 256, MM_SMEM>>>(scale2, nullptr, edge_index, edge_attrs);
    }

    // 5) final linear -> message part of output
    msg_kernel<<<NN / 8, 128>>>(W_lin0, W_lin1, out);

    (void)in_sizes; (void)n_in; (void)out_size;
}

// round 14
// speedup vs baseline: 1.1965x; 1.1965x over previous
#include <cuda_runtime.h>
#include <cuda_bf16.h>
#include <math.h>
#include <stdint.h>

#define NN 10000
#define NE 160000
#define CC 128
#define DD 64
#define HID 256
#define TPWN 512
#define MROW 1024          // m0 (256) + m1 (256*3)
#define SC_OFF (NN * 512)  // message is N*128*4 = N*512 floats, sc follows

#define KP1 448            // layer-1 virtual K': [hi 136+8p | lo 136+8p | hi 136+8p | 16p]
#define KPH 768            // hidden virtual K': [hi 256 | lo 256 | hi 256]
#define KACT 512           // stored activation cols: [hi 256 | lo 256]

// -------- device scratch (allocation-free rule: static __device__ globals) ----
// Only referenced from device code (host-side use binds the host shadow; round-5 bug).
__device__ float g_u0[NN * CC];
__device__ float g_u1[NN * CC * 3];
__device__ float g_down[NN * DD];
__device__ float g_tpw[NE * TPWN];
__device__ float g_m[NN * MROW];

// CSR binning of edges by receiver
__device__ int g_cnt[NN];
__device__ int g_off[NN + 1];
__device__ int g_run[NN];
__device__ int g_elist[NE];

__device__ __align__(16) __nv_bfloat16 g_act0[(size_t)NE * KACT];  // ping [hi|lo]
__device__ __align__(16) __nv_bfloat16 g_act1[(size_t)NE * KACT];  // pong
__device__ __align__(16) __nv_bfloat16 g_w1T[HID * KP1];           // W1^T split [256][448]
__device__ __align__(16) __nv_bfloat16 g_w2T[HID * KPH];           // [256][768] [hi|hi|lo]
__device__ __align__(16) __nv_bfloat16 g_w3T[HID * KPH];
__device__ __align__(16) __nv_bfloat16 g_w4T[TPWN * KPH];          // [512][768]

// ======================= warp-MMA helpers (sm_80+ ISA only) =================
__device__ __forceinline__ uint32_t smem_u32(const void* p) {
    uint32_t a;
    asm("{ .reg .u64 t; cvta.to.shared.u64 t, %1; cvt.u32.u64 %0, t; }" : "=r"(a) : "l"(p));
    return a;
}
#define SW128(off) ((off) ^ (((off) >> 3) & 0x70))

__device__ __forceinline__ void ldm_x4(uint32_t* r, uint32_t addr) {
    asm volatile("ldmatrix.sync.aligned.m8n8.x4.shared.b16 {%0,%1,%2,%3}, [%4];"
                 : "=r"(r[0]), "=r"(r[1]), "=r"(r[2]), "=r"(r[3]) : "r"(addr));
}
__device__ __forceinline__ void mma16816(float* c, const uint32_t* a, const uint32_t* b) {
    asm volatile(
        "mma.sync.aligned.m16n8k16.row.col.f32.bf16.bf16.f32 "
        "{%0,%1,%2,%3}, {%4,%5,%6,%7}, {%8,%9}, {%0,%1,%2,%3};"
        : "+f"(c[0]), "+f"(c[1]), "+f"(c[2]), "+f"(c[3])
        : "r"(a[0]), "r"(a[1]), "r"(a[2]), "r"(a[3]), "r"(b[0]), "r"(b[1]));
}
__device__ __forceinline__ void cp16(uint32_t dst, const void* src) {
    asm volatile("cp.async.cg.shared.global [%0], [%1], 16;" :: "r"(dst), "l"(src));
}
#define CP_COMMIT() asm volatile("cp.async.commit_group;" ::: "memory")
#define CP_WAIT1()  asm volatile("cp.async.wait_group 1;" ::: "memory")
#define CP_WAIT0()  asm volatile("cp.async.wait_group 0;" ::: "memory")

// ---------------------------------------------------------------------------
// CSR binning: zero counters -> histogram -> block scan -> positional scatter
// ---------------------------------------------------------------------------
__global__ void csr_zero_kernel() {
    int i = blockIdx.x * blockDim.x + threadIdx.x;
    if (i < NN) { g_cnt[i] = 0; g_run[i] = 0; }
}

__global__ void csr_hist_kernel(const int* __restrict__ eidx) {
    int e = blockIdx.x * blockDim.x + threadIdx.x;
    if (e < NE) atomicAdd(&g_cnt[eidx[NE + e]], 1);
}

__global__ void csr_scan_kernel() {  // single block, 1024 threads
    __shared__ int ssum[1024];
    __shared__ int carry;
    int tid = threadIdx.x;
    if (tid == 0) carry = 0;
    __syncthreads();
    for (int base = 0; base < NN; base += 1024) {
        int v = (base + tid < NN) ? g_cnt[base + tid] : 0;
        ssum[tid] = v;
        __syncthreads();
#pragma unroll
        for (int off = 1; off < 1024; off <<= 1) {
            int t = (tid >= off) ? ssum[tid - off] : 0;
            __syncthreads();
            ssum[tid] += t;
            __syncthreads();
        }
        if (base + tid < NN) g_off[base + tid] = carry + (ssum[tid] - v);
        __syncthreads();
        if (tid == 0) carry += ssum[1023];
        __syncthreads();
    }
    if (tid == 0) g_off[NN] = carry;  // == NE
}

__global__ void csr_scatter_kernel(const int* __restrict__ eidx) {
    int e = blockIdx.x * blockDim.x + threadIdx.x;
    if (e < NE) {
        int rcv = eidx[NE + e];
        int pos = atomicAdd(&g_run[rcv], 1);
        g_elist[g_off[rcv] + pos] = e;
    }
}

// ---------------------------------------------------------------------------
// Node transforms: u0, u1, down (to scratch) + sc (directly to output)
// ---------------------------------------------------------------------------
__global__ void node_kernel(const float* __restrict__ nf,
                            const float* __restrict__ Wu0,
                            const float* __restrict__ Wu1,
                            const float* __restrict__ Wd,
                            const float* __restrict__ Ws0,
                            const float* __restrict__ Ws1,
                            float* __restrict__ out) {
    const int NB = 8;
    __shared__ float sx0[NB][CC];
    __shared__ float sx1[NB][CC * 3];
    int n0 = blockIdx.x * NB;
    int v = threadIdx.x;  // 0..127

    for (int j = v; j < NB * 512; j += 128) {
        int nb = j >> 9;
        int k = j & 511;
        float val = nf[(size_t)(n0 + nb) * 512 + k];
        if (k < 128) sx0[nb][k] = val;
        else sx1[nb][k - 128] = val;
    }
    __syncthreads();

    const float inv_c = 0.08838834764831845f;  // 1/sqrt(128)

    float au0[NB], as0[NB], ad[NB];
#pragma unroll
    for (int nb = 0; nb < NB; nb++) { au0[nb] = 0.f; as0[nb] = 0.f; ad[nb] = 0.f; }
    for (int u = 0; u < CC; u++) {
        float w0 = Wu0[u * CC + v];
        float ws = Ws0[u * CC + v];
        float wd = (v < DD) ? Wd[u * DD + v] : 0.f;
#pragma unroll
        for (int nb = 0; nb < NB; nb++) {
            float x = sx0[nb][u];
            au0[nb] += x * w0;
            as0[nb] += x * ws;
            ad[nb] += x * wd;
        }
    }
#pragma unroll
    for (int nb = 0; nb < NB; nb++) {
        int n = n0 + nb;
        g_u0[n * CC + v] = au0[nb] * inv_c;
        out[SC_OFF + (size_t)n * 512 + v] = as0[nb] * inv_c;
        if (v < DD) g_down[n * DD + v] = ad[nb] * inv_c;
    }

    float au1[NB][3], as1[NB][3];
#pragma unroll
    for (int nb = 0; nb < NB; nb++)
#pragma unroll
        for (int i = 0; i < 3; i++) { au1[nb][i] = 0.f; as1[nb][i] = 0.f; }
    for (int u = 0; u < CC; u++) {
        float wu = Wu1[u * CC + v];
        float ws = Ws1[u * CC + v];
#pragma unroll
        for (int nb = 0; nb < NB; nb++) {
#pragma unroll
            for (int i = 0; i < 3; i++) {
                float x = sx1[nb][u * 3 + i];
                au1[nb][i] += x * wu;
                as1[nb][i] += x * ws;
            }
        }
    }
#pragma unroll
    for (int nb = 0; nb < NB; nb++) {
        int n = n0 + nb;
#pragma unroll
        for (int i = 0; i < 3; i++) {
            g_u1[n * (CC * 3) + v * 3 + i] = au1[nb][i] * inv_c;
            out[SC_OFF + (size_t)n * 512 + 128 + v * 3 + i] = as1[nb][i] * inv_c;
        }
    }
}

// ---------------------------------------------------------------------------
// Weight prep: transpose to [N][K'] K-major bf16 with split segments.
// ---------------------------------------------------------------------------
__global__ void prep_w1(const float* __restrict__ w) {  // [136][256] -> g_w1T [256][448]
    int i = blockIdx.x * blockDim.x + threadIdx.x;
    if (i >= HID * KP1) return;
    int n = i / KP1, k = i % KP1;
    __nv_bfloat16 o = __float2bfloat16(0.f);
    if (k < 432) {
        int seg = k / 144, rem = k % 144;
        if (rem < 136) {
            float v = w[rem * HID + n];
            __nv_bfloat16 h = __float2bfloat16(v);
            o = (seg < 2) ? h : __float2bfloat16(v - __bfloat162float(h));
        }
    }
    g_w1T[n * KP1 + k] = o;
}

template <int WSEL>  // 2,3,4
__global__ void prep_w_hid(const float* __restrict__ w, int Nc) {
    int i = blockIdx.x * blockDim.x + threadIdx.x;
    if (i >= Nc * KPH) return;
    int n = i / KPH, k = i % KPH;
    int seg = k >> 8, rem = k & 255;
    float v = w[rem * Nc + n];
    __nv_bfloat16 h = __float2bfloat16(v);
    __nv_bfloat16 o = (seg < 2) ? h : __float2bfloat16(v - __bfloat162float(h));
    __nv_bfloat16* dst = (WSEL == 2) ? g_w2T : (WSEL == 3) ? g_w3T : g_w4T;
    dst[(size_t)n * KPH + k] = o;
}

// ---------------------------------------------------------------------------
// HMMA GEMM: C[128 x 128 tile] = A'[M,K'] @ W'[N,K']^T, fp32 accum.
// 8 warps: 4(M) x 2(N) -> warp tile 32x64. mma.m16n8k16 bf16, ldmatrix feeds.
// 3-stage cp.async ring, K staged 64 bf16 (128B SW128 rows).
// SRC 0: A gathered+split on the fly from fp32 (edge_feats | down[s] | down[r]).
// SRC 1/2: A = g_act0/g_act1 stored [hi|lo]; virtual col>=512 re-reads hi.
// DST 0/1 -> silu + bf16 hi/lo split into g_act0/g_act1; 2 -> fp32 g_tpw.
// ---------------------------------------------------------------------------
template <int SRC, int WSEL, int DST, int KPRM, bool SILU>
__global__ void __launch_bounds__(256)
mma_gemm(float scale, const float* __restrict__ ef, const int* __restrict__ eidx) {
    const __nv_bfloat16* __restrict__ A =
        (SRC == 1) ? g_act0 : (SRC == 2) ? g_act1 : nullptr;
    const __nv_bfloat16* __restrict__ W =
        (WSEL == 1) ? g_w1T : (WSEL == 2) ? g_w2T : (WSEL == 3) ? g_w3T : g_w4T;
    const int WK = (WSEL == 1) ? KP1 : KPH;  // weight row stride

    extern __shared__ char smem[];
    const int BOFF = 49152;  // A: 3 x 16KB, B: 3 x 16KB
    uint32_t sb = smem_u32(smem);

    int tid = threadIdx.x;
    int lane = tid & 31, wid = tid >> 5;
    int wm = wid & 3;        // 0..3 -> M offset wm*32
    int wn = wid >> 2;       // 0..1 -> N offset wn*64
    int rowBase = blockIdx.y * 128;
    int colBase = blockIdx.x * 128;
    const int S = KPRM / 64;

    float acc[2][8][4];
#pragma unroll
    for (int i = 0; i < 2; i++)
#pragma unroll
        for (int j = 0; j < 8; j++)
#pragma unroll
            for (int q = 0; q < 4; q++) acc[i][j][q] = 0.f;

    // ---- stage loader: A tile 128x64 bf16 + B tile 128x64 bf16, SW128 ----
    auto load_stage = [&](int ks, int buf) {
        char* as = smem + buf * 16384;
        uint32_t bBase = sb + BOFF + buf * 16384;
        uint32_t aBase = sb + buf * 16384;
#pragma unroll
        for (int c = 0; c < 4; c++) {
            int idx = tid + c * 256;           // 0..1023
            int row = idx >> 3, cb = idx & 7;  // 128 rows x 8 chunks of 8 bf16
            int c0 = ks * 64 + cb * 8;
            uint32_t so = SW128((uint32_t)(row * 128 + cb * 16));
            // ---- A ----
            if (SRC == 0) {
                float v[8];
                bool zero = (c0 >= 432);
                int seg = 0;
                if (!zero) {
                    seg = c0 / 144;            // 0,1,2
                    int j = c0 - seg * 144;
                    const float* src = nullptr;
                    int e = rowBase + row;
                    if (j < 8) src = ef + (size_t)e * 8 + j;
                    else if (j < 72) src = g_down + (size_t)eidx[e] * DD + (j - 8);
                    else if (j < 136) src = g_down + (size_t)eidx[NE + e] * DD + (j - 72);
                    else zero = true;          // pad cols 136..143 within segment
                    if (!zero) {
                        float4 v0 = *(const float4*)src;
                        float4 v1 = *(const float4*)(src + 4);
                        v[0] = v0.x; v[1] = v0.y; v[2] = v0.z; v[3] = v0.w;
                        v[4] = v1.x; v[5] = v1.y; v[6] = v1.z; v[7] = v1.w;
                    }
                }
                uint4 wv;
                if (zero) {
                    wv = make_uint4(0u, 0u, 0u, 0u);
                } else {
                    uint32_t pk[4];
#pragma unroll
                    for (int t = 0; t < 4; t++) {
                        __nv_bfloat16 h0 = __float2bfloat16(v[2 * t]);
                        __nv_bfloat16 h1 = __float2bfloat16(v[2 * t + 1]);
                        __nv_bfloat162 p;
                        if (seg == 1) {
                            p.x = __float2bfloat16(v[2 * t] - __bfloat162float(h0));
                            p.y = __float2bfloat16(v[2 * t + 1] - __bfloat162float(h1));
                        } else {
                            p.x = h0; p.y = h1;
                        }
                        pk[t] = *(uint32_t*)&p;
                    }
                    wv = make_uint4(pk[0], pk[1], pk[2], pk[3]);
                }
                *(uint4*)(as + so) = wv;
            } else {
                int srccol = (c0 < KACT) ? c0 : c0 - KACT;  // hi copy re-read
                cp16(aBase + so, A + (size_t)(rowBase + row) * KACT + srccol);
            }
            // ---- B (always dense, cp.async) ----
            cp16(bBase + so, W + (size_t)(colBase + row) * WK + c0);
        }
        CP_COMMIT();
    };

    load_stage(0, 0);
    if (S > 1) load_stage(1, 1);

    for (int s = 0; s < S; s++) {
        if (s + 1 < S) { CP_WAIT1(); } else { CP_WAIT0(); }
        __syncthreads();

        int buf = s % 3;
        uint32_t aBase = sb + buf * 16384;
        uint32_t bBase = sb + BOFF + buf * 16384;
#pragma unroll
        for (int k16 = 0; k16 < 4; k16++) {
            uint32_t a[2][4];
#pragma unroll
            for (int mf = 0; mf < 2; mf++) {
                int r = wm * 32 + mf * 16 + (lane & 15);
                int kc = k16 * 16 + ((lane >> 4) << 3);
                ldm_x4(a[mf], aBase + SW128((uint32_t)(r * 128 + kc * 2)));
            }
            uint32_t b[8][2];
#pragma unroll
            for (int g = 0; g < 4; g++) {
                int nr = wn * 64 + g * 16 + (lane & 7) + ((lane >> 4) & 1) * 8;
                int kc = k16 * 16 + (((lane >> 3) & 1) << 3);
                uint32_t t4[4];
                ldm_x4(t4, bBase + SW128((uint32_t)(nr * 128 + kc * 2)));
                b[2 * g][0] = t4[0]; b[2 * g][1] = t4[1];
                b[2 * g + 1][0] = t4[2]; b[2 * g + 1][1] = t4[3];
            }
#pragma unroll
            for (int mf = 0; mf < 2; mf++)
#pragma unroll
                for (int nf = 0; nf < 8; nf++)
                    mma16816(acc[mf][nf], a[mf], b[nf]);
        }
        __syncthreads();  // all reads of buf done before refill

        if (s + 2 < S) load_stage(s + 2, (s + 2) % 3);
    }

    // ---- epilogue: frag (mf,nf): rows r0,r0+8; cols c0,c0+1 ----
#pragma unroll
    for (int mf = 0; mf < 2; mf++) {
#pragma unroll
        for (int nf = 0; nf < 8; nf++) {
            int r0 = rowBase + wm * 32 + mf * 16 + (lane >> 2);
            int c0 = colBase + wn * 64 + nf * 8 + (lane & 3) * 2;
            if (DST == 2) {
                float2 v0 = make_float2(acc[mf][nf][0] * scale, acc[mf][nf][1] * scale);
                float2 v1 = make_float2(acc[mf][nf][2] * scale, acc[mf][nf][3] * scale);
                *(float2*)(g_tpw + (size_t)r0 * TPWN + c0) = v0;
                *(float2*)(g_tpw + (size_t)(r0 + 8) * TPWN + c0) = v1;
            } else {
                __nv_bfloat16* dst = (DST == 0) ? g_act0 : g_act1;
#pragma unroll
                for (int rr = 0; rr < 2; rr++) {
                    float x0 = acc[mf][nf][rr * 2 + 0] * scale;
                    float x1 = acc[mf][nf][rr * 2 + 1] * scale;
                    if (SILU) {
                        x0 = x0 / (1.0f + expf(-x0));
                        x1 = x1 / (1.0f + expf(-x1));
                    }
                    __nv_bfloat16 h0 = __float2bfloat16(x0);
                    __nv_bfloat16 h1 = __float2bfloat16(x1);
                    __nv_bfloat162 hp; hp.x = h0; hp.y = h1;
                    __nv_bfloat162 lp;
                    lp.x = __float2bfloat16(x0 - __bfloat162float(h0));
                    lp.y = __float2bfloat16(x1 - __bfloat162float(h1));
                    __nv_bfloat16* p = dst + (size_t)(r0 + rr * 8) * KACT + c0;
                    *(__nv_bfloat162*)(p) = hp;          // hi segment [0,256)
                    *(__nv_bfloat162*)(p + 256) = lp;    // lo segment [256,512)
                }
            }
        }
    }
}

// ---------------------------------------------------------------------------
// Gather tensor-product: one block per receiver node, thread = channel.
// Accumulates all TP terms over the node's CSR edge list in registers,
// writes its g_m row exactly once. NO atomics.
// ---------------------------------------------------------------------------
__global__ void gather_tp_kernel(const float* __restrict__ ea,
                                 const int* __restrict__ eidx) {
    int n = blockIdx.x;
    int c = threadIdx.x;  // 0..127
    int beg = g_off[n], end = g_off[n + 1];

    float m0a = 0.f, m0b = 0.f;
    float m1a0 = 0.f, m1a1 = 0.f, m1a2 = 0.f;
    float m1b0 = 0.f, m1b1 = 0.f, m1b2 = 0.f;
    const float rsqrt3 = 0.5773502691896258f;

    for (int i = beg; i < end; i++) {
        int e = g_elist[i];
        int snd = eidx[e];
        float4 y = *(const float4*)(ea + (size_t)e * 4);
        const float* tw = g_tpw + (size_t)e * TPWN;
        float w0 = tw[c];
        float w1 = tw[128 + c];
        float w2 = tw[256 + c];
        float w3 = tw[384 + c];
        float xs0 = g_u0[(size_t)snd * CC + c];
        const float* u1p = g_u1 + (size_t)snd * (CC * 3) + c * 3;
        float x1a = u1p[0], x1b = u1p[1], x1c = u1p[2];

        m0a += w0 * xs0 * y.x;
        m0b += w3 * (x1a * y.y + x1b * y.z + x1c * y.w) * rsqrt3;
        float a = w1 * xs0;
        m1a0 += a * y.y; m1a1 += a * y.z; m1a2 += a * y.w;
        float b = w2 * y.x;
        m1b0 += b * x1a; m1b1 += b * x1b; m1b2 += b * x1c;
    }

    float* mrow = g_m + (size_t)n * MROW;
    mrow[c] = m0a;
    mrow[128 + c] = m0b;
    mrow[256 + c * 3 + 0] = m1a0;
    mrow[256 + c * 3 + 1] = m1a1;
    mrow[256 + c * 3 + 2] = m1a2;
    mrow[256 + (128 + c) * 3 + 0] = m1b0;
    mrow[256 + (128 + c) * 3 + 1] = m1b1;
    mrow[256 + (128 + c) * 3 + 2] = m1b2;
}

// ---------------------------------------------------------------------------
// Final linear: message[n,v,0] = (m0 @ Wl0)/256 ; message[n,v,1..3] = (m1 @ Wl1)/256
// ---------------------------------------------------------------------------
__global__ void msg_kernel(const float* __restrict__ Wl0,
                           const float* __restrict__ Wl1,
                           float* __restrict__ out) {
    const int NB = 8;
    __shared__ float sm[NB][MROW];
    int n0 = blockIdx.x * NB;
    int v = threadIdx.x;

    for (int j = v; j < NB * MROW; j += 128) {
        sm[j >> 10][j & 1023] = g_m[(size_t)n0 * MROW + j];
    }
    __syncthreads();

    float m0acc[NB];
    float m1acc[NB][3];
#pragma unroll
    for (int nb = 0; nb < NB; nb++) {
        m0acc[nb] = 0.f;
#pragma unroll
        for (int i = 0; i < 3; i++) m1acc[nb][i] = 0.f;
    }

    for (int cc = 0; cc < 256; cc++) {
        float w0 = Wl0[cc * 128 + v];
        float w1 = Wl1[cc * 128 + v];
#pragma unroll
        for (int nb = 0; nb < NB; nb++) {
            m0acc[nb] += sm[nb][cc] * w0;
#pragma unroll
            for (int i = 0; i < 3; i++)
                m1acc[nb][i] += sm[nb][256 + cc * 3 + i] * w1;
        }
    }

    const float sc = 1.0f / 256.0f;  // (1/sqrt(256)) / AVG_NEIGH
#pragma unroll
    for (int nb = 0; nb < NB; nb++) {
        int n = n0 + nb;
        float4 v4;
        v4.x = m0acc[nb] * sc;
        v4.y = m1acc[nb][0] * sc;
        v4.z = m1acc[nb][1] * sc;
        v4.w = m1acc[nb][2] * sc;
        *(float4*)(out + (size_t)n * 512 + v * 4) = v4;
    }
}

// ---------------------------------------------------------------------------
extern "C" void kernel_launch(void* const* d_in, const int* in_sizes, int n_in,
                              void* d_out, int out_size) {
    const float* node_feats = (const float*)d_in[1];
    const float* edge_attrs = (const float*)d_in[2];
    const float* edge_feats = (const float*)d_in[3];
    const int*   edge_index = (const int*)d_in[4];
    const float* W_up0  = (const float*)d_in[5];
    const float* W_up1  = (const float*)d_in[6];
    const float* W_down = (const float*)d_in[7];
    const float* mlp_w1 = (const float*)d_in[8];
    const float* mlp_w2 = (const float*)d_in[9];
    const float* mlp_w3 = (const float*)d_in[10];
    const float* mlp_w4 = (const float*)d_in[11];
    const float* W_lin0 = (const float*)d_in[12];
    const float* W_lin1 = (const float*)d_in[13];
    const float* W_skip0 = (const float*)d_in[14];
    const float* W_skip1 = (const float*)d_in[15];
    float* out = (float*)d_out;

    const int MM_SMEM = 98304;  // 3x16KB A + 3x16KB B
    cudaFuncSetAttribute(mma_gemm<0, 1, 0, KP1, true>,
                         cudaFuncAttributeMaxDynamicSharedMemorySize, MM_SMEM);
    cudaFuncSetAttribute(mma_gemm<1, 2, 1, KPH, true>,
                         cudaFuncAttributeMaxDynamicSharedMemorySize, MM_SMEM);
    cudaFuncSetAttribute(mma_gemm<2, 3, 0, KPH, true>,
                         cudaFuncAttributeMaxDynamicSharedMemorySize, MM_SMEM);
    cudaFuncSetAttribute(mma_gemm<1, 4, 2, KPH, false>,
                         cudaFuncAttributeMaxDynamicSharedMemorySize, MM_SMEM);

    // 1) CSR binning of edges by receiver (replaces the atomic scatter)
    csr_zero_kernel<<<(NN + 255) / 256, 256>>>();
    csr_hist_kernel<<<(NE + 255) / 256, 256>>>(edge_index);
    csr_scan_kernel<<<1, 1024>>>();
    csr_scatter_kernel<<<(NE + 255) / 256, 256>>>(edge_index);

    // 2) node transforms (+ sc output); produces g_down / g_u0 / g_u1
    node_kernel<<<NN / 8, 128>>>(node_feats, W_up0, W_up1, W_down, W_skip0, W_skip1, out);

    // 3) weight prep (transpose + bf16 hi/lo split)
    prep_w1<<<(HID * KP1 + 255) / 256, 256>>>(mlp_w1);
    prep_w_hid<2><<<(HID * KPH + 255) / 256, 256>>>(mlp_w2, HID);
    prep_w_hid<3><<<(HID * KPH + 255) / 256, 256>>>(mlp_w3, HID);
    prep_w_hid<4><<<(TPWN * KPH + 255) / 256, 256>>>(mlp_w4, TPWN);

    // 4) edge MLP on HMMA tensor cores; layer-1 gathers its operand on the fly
    float scale1 = 1.0f / sqrtf(136.0f);
    float scale2 = 1.0f / 16.0f;
    {
        dim3 g(HID / 128, NE / 128);   // (2, 1250)
        mma_gemm<0, 1, 0, KP1, true><<<g, 256, MM_SMEM>>>(scale1, edge_feats, edge_index);
        mma_gemm<1, 2, 1, KPH, true><<<g, 256, MM_SMEM>>>(scale2, nullptr, nullptr);
        mma_gemm<2, 3, 0, KPH, true><<<g, 256, MM_SMEM>>>(scale2, nullptr, nullptr);
    }
    {
        dim3 g(TPWN / 128, NE / 128);  // (4, 1250)
        mma_gemm<1, 4, 2, KPH, false><<<g, 256, MM_SMEM>>>(scale2, nullptr, nullptr);
    }

    // 5) gather tensor product per receiver node (atomic-free segment sum)
    gather_tp_kernel<<<NN, 128>>>(edge_attrs, edge_index);

    // 6) final linear -> message part of output
    msg_kernel<<<NN / 8, 128>>>(W_lin0, W_lin1, out);

    (void)in_sizes; (void)n_in; (void)out_size;
}